// round 9
// baseline (speedup 1.0000x reference)
#include <cuda_runtime.h>
#include <cuda_bf16.h>
#include <math.h>

// Problem constants (match reference)
#define NBX     512
#define NBY     512
#define BSX     1.953125f   // 1000/512, exact in fp32
#define BSY     1.953125f
#define INV_BS  0.512f      // rn(1/BSX); floor corrected exactly below
#define INV_UPC 10.0f       // 1 / UNIT_PIN_CAP

// Quad map: Q[bx][by] = {u[bx][by], u[bx][by1], u[bx1][by], u[bx1][by1]},
// bx1 = min(bx+1,511), by1 = min(by+1,511). 4 MB static device scratch.
__device__ float4 g_quad[NBX * NBY];

__global__ __launch_bounds__(256) void build_quad_kernel(
    const float* __restrict__ umap)
{
    int idx = blockIdx.x * blockDim.x + threadIdx.x;
    if (idx >= NBX * NBY) return;
    int bx = idx >> 9;
    int by = idx & (NBY - 1);
    int bx1 = min(bx + 1, NBX - 1);
    int by1 = min(by + 1, NBY - 1);
    const float* r0 = umap + bx  * NBY;
    const float* r1 = umap + bx1 * NBY;
    float4 q;
    q.x = __ldg(&r0[by]);
    q.y = __ldg(&r0[by1]);
    q.z = __ldg(&r1[by]);
    q.w = __ldg(&r1[by1]);
    g_quad[idx] = q;
}

// Branchless exact floor of x/BS: start from fast product, then correct with
// EXACT comparisons (b*BSX is exactly representable for integer b in [0,512]).
// Result provably equals floorf(__fdiv_rn(x, BSX)) for x in [0, 999).
__device__ __forceinline__ float exact_bin_floor(float x) {
    float fb = floorf(x * INV_BS);
    fb += ((fb + 1.0f) * BSX <= x) ? 1.0f : 0.0f;   // under-estimate fix
    fb -= (fb * BSX > x)           ? 1.0f : 0.0f;   // over-estimate fix
    return fb;
}

// B-stage: bins + overlaps + issue the quad gather. Returns weights and the
// pending float4 via out-params.
__device__ __forceinline__ void b_stage(
    float x, float y, float w, float h, float p,
    float& ox0, float& ox1, float& oy0, float& oy1,
    float& k, float4& u)
{
    float fbx = exact_bin_floor(x);
    float fby = exact_bin_floor(y);

    float hix = x + w;
    float hiy = y + h;

    // Overlaps use UNCLIPPED bin positions (exactly as reference)
    float blx0 = fbx * BSX;
    ox0 = fmaxf(fminf(hix, blx0 + BSX)        - fmaxf(x, blx0),       0.0f);
    ox1 = fmaxf(fminf(hix, blx0 + 2.0f * BSX) - fmaxf(x, blx0 + BSX), 0.0f);

    float bly0 = fby * BSY;
    oy0 = fmaxf(fminf(hiy, bly0 + BSY)        - fmaxf(y, bly0),       0.0f);
    oy1 = fmaxf(fminf(hiy, bly0 + 2.0f * BSY) - fmaxf(y, bly0 + BSY), 0.0f);

    // x,y in [0,999) -> indices already in [0,511]; no clamp needed.
    int qidx = ((int)fbx << 9) | (int)fby;
    u = __ldg(&g_quad[qidx]);             // issued here, consumed next iter

    k = __fdividef(p * INV_UPC, w * h);
}

__device__ __forceinline__ float c_stage(
    float ox0, float ox1, float oy0, float oy1, float k, float4 u)
{
    float area = ox0 * (oy0 * u.x + oy1 * u.y)
               + ox1 * (oy0 * u.z + oy1 * u.w);
    return area * k;
}

// 1 node/thread, grid-stride, 3-stage software pipeline:
//   iter i: prefetch S[i+1]  |  B-stage(i): bins + issue gather  |
//           C-stage(i-1): consume gather, store
__global__ __launch_bounds__(256) void node_area_kernel_v11(
    const float* __restrict__ pos,        // [2N]: x then y
    const float* __restrict__ nsx,        // [N]
    const float* __restrict__ nsy,        // [N]
    const int*   __restrict__ pw,         // [N]
    float*       __restrict__ out,        // [N]
    int n)
{
    int i = blockIdx.x * blockDim.x + threadIdx.x;
    int stride = gridDim.x * blockDim.x;
    if (i >= n) return;

    // Prologue: load S(i), run B(i) (latency exposed once only)
    float cx = __ldg(&pos[i]);
    float cy = __ldg(&pos[n + i]);
    float cw = __ldg(&nsx[i]);
    float ch = __ldg(&nsy[i]);
    float cp = (float)__ldg(&pw[i]);

    float ox0, ox1, oy0, oy1, k;
    float4 u;
    b_stage(cx, cy, cw, ch, cp, ox0, ox1, oy0, oy1, k, u);
    int iprev = i;

    i += stride;
    if (i < n) {
        // preload S(i) for the first loop pass
        cx = __ldg(&pos[i]);
        cy = __ldg(&pos[n + i]);
        cw = __ldg(&nsx[i]);
        ch = __ldg(&nsy[i]);
        cp = (float)__ldg(&pw[i]);

        while (true) {
            int inext = i + stride;
            bool more = inext < n;

            // (a) prefetch streaming data for i+1
            float nx2, ny2, nw2, nh2, np2;
            if (more) {
                nx2 = __ldg(&pos[inext]);
                ny2 = __ldg(&pos[n + inext]);
                nw2 = __ldg(&nsx[inext]);
                nh2 = __ldg(&nsy[inext]);
                np2 = (float)__ldg(&pw[inext]);
            }

            // (b) B-stage for i (streaming data arrived an iteration ago)
            float tox0, tox1, toy0, toy1, tk;
            float4 tu;
            b_stage(cx, cy, cw, ch, cp, tox0, tox1, toy0, toy1, tk, tu);

            // (c) C-stage for i-1 (gather issued one full iteration ago)
            out[iprev] = c_stage(ox0, ox1, oy0, oy1, k, u);

            // rotate
            ox0 = tox0; ox1 = tox1; oy0 = toy0; oy1 = toy1; k = tk; u = tu;
            iprev = i;

            if (!more) break;
            cx = nx2; cy = ny2; cw = nw2; ch = nh2; cp = np2;
            i = inext;
        }
    }

    // Epilogue: final pending C-stage
    out[iprev] = c_stage(ox0, ox1, oy0, oy1, k, u);
}

extern "C" void kernel_launch(void* const* d_in, const int* in_sizes, int n_in,
                              void* d_out, int out_size)
{
    const float* pos  = (const float*)d_in[0];
    const float* nsx  = (const float*)d_in[1];
    const float* nsy  = (const float*)d_in[2];
    const float* umap = (const float*)d_in[3];
    const int*   pw   = (const int*)d_in[4];
    float*       out  = (float*)d_out;

    int n = in_sizes[1];  // node_size_x has N elements

    // Pass 1: build the quad map (clip-at-edge baked in)
    {
        int total = NBX * NBY;
        int threads = 256;
        int blocks = (total + threads - 1) / threads;
        build_quad_kernel<<<blocks, threads>>>(umap);
    }

    // Pass 2: pipelined grid-stride, ~6-7 iterations per thread
    {
        int threads = 256;
        int blocks = 148 * 8;
        node_area_kernel_v11<<<blocks, threads>>>(pos, nsx, nsy, pw, out, n);
    }
}

// round 12
// speedup vs baseline: 1.0928x; 1.0928x over previous
#include <cuda_runtime.h>
#include <cuda_bf16.h>
#include <cuda_fp16.h>
#include <math.h>

// Problem constants (match reference)
#define NBX     512
#define NBY     512
#define BSX     1.953125f   // 1000/512, exact in fp32
#define BSY     1.953125f
#define INV_BS  0.512f      // rn(1/BSX); floor corrected exactly below
#define INV_UPC 10.0f       // 1 / UNIT_PIN_CAP

// Half-precision quad map: Q[bx][by] = {u00,u01,u10,u11} packed into a uint2
// (two half2 words, 8B). +1 clips baked in. 2 MB static device scratch.
__device__ uint2 g_quad_h[NBX * NBY];

__device__ __forceinline__ unsigned pack_half2(float a, float b) {
    __half2 h = __floats2half2_rn(a, b);
    return *reinterpret_cast<unsigned*>(&h);
}

__device__ __forceinline__ float2 unpack_half2(unsigned w) {
    __half2 h = *reinterpret_cast<__half2*>(&w);
    return __half22float2(h);
}

__global__ __launch_bounds__(256) void build_quad_kernel(
    const float* __restrict__ umap)
{
    int idx = blockIdx.x * blockDim.x + threadIdx.x;
    if (idx >= NBX * NBY) return;
    int bx = idx >> 9;
    int by = idx & (NBY - 1);
    int bx1 = min(bx + 1, NBX - 1);
    int by1 = min(by + 1, NBY - 1);
    const float* r0 = umap + bx  * NBY;
    const float* r1 = umap + bx1 * NBY;
    uint2 q;
    q.x = pack_half2(__ldg(&r0[by]), __ldg(&r0[by1]));  // u00,u01
    q.y = pack_half2(__ldg(&r1[by]), __ldg(&r1[by1]));  // u10,u11
    g_quad_h[idx] = q;
}

// Branchless exact floor of x/BS: fast product then exact correction
// (b*BSX exactly representable for integer b in [0,512]). Provably equals
// floorf(div.rn(x, BSX)) for x in [0, 999).
__device__ __forceinline__ float exact_bin_floor(float x) {
    float fb = floorf(x * INV_BS);
    fb += ((fb + 1.0f) * BSX <= x) ? 1.0f : 0.0f;
    fb -= (fb * BSX > x)           ? 1.0f : 0.0f;
    return fb;
}

__device__ __forceinline__ float node_area(
    float x, float y, float w, float h, float ps)
{
    float fbx = exact_bin_floor(x);
    float fby = exact_bin_floor(y);

    float hix = x + w;
    float hiy = y + h;

    // Overlaps use UNCLIPPED bin positions (as in reference)
    float blx0 = fbx * BSX;
    float ox0 = fmaxf(fminf(hix, blx0 + BSX)        - fmaxf(x, blx0),       0.0f);
    float ox1 = fmaxf(fminf(hix, blx0 + 2.0f * BSX) - fmaxf(x, blx0 + BSX), 0.0f);

    float bly0 = fby * BSY;
    float oy0 = fmaxf(fminf(hiy, bly0 + BSY)        - fmaxf(y, bly0),       0.0f);
    float oy1 = fmaxf(fminf(hiy, bly0 + 2.0f * BSY) - fmaxf(y, bly0 + BSY), 0.0f);

    // x,y in [0,999) -> indices already in [0,511]; +1 clip baked into map.
    int qidx = ((int)fbx << 9) | (int)fby;

    // Single 8-byte gather (one LDG.64).
    uint2 q = __ldg(&g_quad_h[qidx]);

    float2 ulo = unpack_half2(q.x);  // u00,u01
    float2 uhi = unpack_half2(q.y);  // u10,u11

    float area = ox0 * (oy0 * ulo.x + oy1 * ulo.y)
               + ox1 * (oy0 * uhi.x + oy1 * uhi.y);

    return __fdividef(area * ps, w * h);
}

// v10 structure: grid-stride, register double-buffered streaming prefetch,
// 2 nodes per thread.
__global__ __launch_bounds__(256, 6) void node_area_kernel_v12(
    const float* __restrict__ pos,        // [2N]: x then y
    const float* __restrict__ nsx,        // [N]
    const float* __restrict__ nsy,        // [N]
    const int*   __restrict__ pw,         // [N]
    float*       __restrict__ out,        // [N]
    int n)
{
    int i = (blockIdx.x * blockDim.x + threadIdx.x) * 2;
    int stride = gridDim.x * blockDim.x * 2;

    if (i >= n) return;

    float2 x2 = *(const float2*)(pos + i);
    float2 y2 = *(const float2*)(pos + n + i);
    float2 w2 = *(const float2*)(nsx + i);
    float2 h2 = *(const float2*)(nsy + i);
    int2   p2 = *(const int2*)(pw + i);

    while (true) {
        int inext = i + stride;
        bool more = inext < n;

        float2 nx, ny, nw, nh; int2 np;
        if (more) {
            nx = *(const float2*)(pos + inext);
            ny = *(const float2*)(pos + n + inext);
            nw = *(const float2*)(nsx + inext);
            nh = *(const float2*)(nsy + inext);
            np = *(const int2*)(pw + inext);
        }

        float2 r;
        r.x = node_area(x2.x, y2.x, w2.x, h2.x, (float)p2.x * INV_UPC);
        r.y = node_area(x2.y, y2.y, w2.y, h2.y, (float)p2.y * INV_UPC);
        *(float2*)(out + i) = r;

        if (!more) break;
        x2 = nx; y2 = ny; w2 = nw; h2 = nh; p2 = np;
        i = inext;
    }
}

extern "C" void kernel_launch(void* const* d_in, const int* in_sizes, int n_in,
                              void* d_out, int out_size)
{
    const float* pos  = (const float*)d_in[0];
    const float* nsx  = (const float*)d_in[1];
    const float* nsy  = (const float*)d_in[2];
    const float* umap = (const float*)d_in[3];
    const int*   pw   = (const int*)d_in[4];
    float*       out  = (float*)d_out;

    int n = in_sizes[1];  // node_size_x has N elements

    // Pass 1: build the half-precision quad map
    {
        int total = NBX * NBY;
        int threads = 256;
        int blocks = (total + threads - 1) / threads;
        build_quad_kernel<<<blocks, threads>>>(umap);
    }

    // Pass 2: grid-stride, register double-buffered, 8B gather per node
    {
        int threads = 256;
        int blocks = 148 * 6;
        node_area_kernel_v12<<<blocks, threads>>>(pos, nsx, nsy, pw, out, n);
    }
}

// round 13
// speedup vs baseline: 1.0990x; 1.0057x over previous
#include <cuda_runtime.h>
#include <cuda_bf16.h>
#include <cuda_fp16.h>
#include <math.h>

// Problem constants (match reference)
#define NBX     512
#define NBY     512
#define BSX     1.953125f   // 1000/512, exact in fp32
#define BSY     1.953125f
#define INV_BS  0.512f      // rn(1/BSX); floor corrected exactly below
#define INV_UPC 10.0f       // 1 / UNIT_PIN_CAP

// Half-precision quad map: Q[bx][by] = {u00,u01,u10,u11} packed into a uint2
// (two half2 words, 8B). +1 clips baked in. 2 MB static device scratch.
__device__ uint2 g_quad_h[NBX * NBY];

__device__ __forceinline__ unsigned pack_half2(float a, float b) {
    __half2 h = __floats2half2_rn(a, b);
    return *reinterpret_cast<unsigned*>(&h);
}

__device__ __forceinline__ float2 unpack_half2(unsigned w) {
    __half2 h = *reinterpret_cast<__half2*>(&w);
    return __half22float2(h);
}

// 2 quad entries per thread.
__global__ __launch_bounds__(256) void build_quad_kernel(
    const float* __restrict__ umap)
{
    int t = blockIdx.x * blockDim.x + threadIdx.x;
    int idx0 = t * 2;
    if (idx0 >= NBX * NBY) return;

    #pragma unroll
    for (int j = 0; j < 2; j++) {
        int idx = idx0 + j;
        int bx = idx >> 9;
        int by = idx & (NBY - 1);
        int bx1 = min(bx + 1, NBX - 1);
        int by1 = min(by + 1, NBY - 1);
        const float* r0 = umap + bx  * NBY;
        const float* r1 = umap + bx1 * NBY;
        uint2 q;
        q.x = pack_half2(__ldg(&r0[by]), __ldg(&r0[by1]));  // u00,u01
        q.y = pack_half2(__ldg(&r1[by]), __ldg(&r1[by1]));  // u10,u11
        g_quad_h[idx] = q;
    }
}

// Branchless exact floor of x/BS: fast product then exact correction
// (b*BSX exactly representable for integer b in [0,512]). Provably equals
// floorf(div.rn(x, BSX)) for x in [0, 999).
__device__ __forceinline__ float exact_bin_floor(float x) {
    float fb = floorf(x * INV_BS);
    fb += ((fb + 1.0f) * BSX <= x) ? 1.0f : 0.0f;
    fb -= (fb * BSX > x)           ? 1.0f : 0.0f;
    return fb;
}

__device__ __forceinline__ float node_area(
    float x, float y, float w, float h, float ps)
{
    float fbx = exact_bin_floor(x);
    float fby = exact_bin_floor(y);

    float hix = x + w;
    float hiy = y + h;

    // Overlaps use UNCLIPPED bin positions (as in reference)
    float blx0 = fbx * BSX;
    float ox0 = fmaxf(fminf(hix, blx0 + BSX)        - fmaxf(x, blx0),       0.0f);
    float ox1 = fmaxf(fminf(hix, blx0 + 2.0f * BSX) - fmaxf(x, blx0 + BSX), 0.0f);

    float bly0 = fby * BSY;
    float oy0 = fmaxf(fminf(hiy, bly0 + BSY)        - fmaxf(y, bly0),       0.0f);
    float oy1 = fmaxf(fminf(hiy, bly0 + 2.0f * BSY) - fmaxf(y, bly0 + BSY), 0.0f);

    // x,y in [0,999) -> indices already in [0,511]; +1 clip baked into map.
    int qidx = ((int)fbx << 9) | (int)fby;

    // Single 8-byte gather (one LDG.64), default caching -> L1-resident map.
    uint2 q = __ldg(&g_quad_h[qidx]);

    float2 ulo = unpack_half2(q.x);  // u00,u01
    float2 uhi = unpack_half2(q.y);  // u10,u11

    float area = ox0 * (oy0 * ulo.x + oy1 * ulo.y)
               + ox1 * (oy0 * uhi.x + oy1 * uhi.y);

    return __fdividef(area * ps, w * h);
}

// Flat, 2 nodes/thread. Streaming traffic uses .cs (evict-first) so L1 stays
// dedicated to the quad map.
__global__ __launch_bounds__(256) void node_area_kernel_v13(
    const float* __restrict__ pos,        // [2N]: x then y
    const float* __restrict__ nsx,        // [N]
    const float* __restrict__ nsy,        // [N]
    const int*   __restrict__ pw,         // [N]
    float*       __restrict__ out,        // [N]
    int n)
{
    int i = (blockIdx.x * blockDim.x + threadIdx.x) * 2;
    if (i >= n) return;
    // N is even; full float2 accesses are always valid.

    float2 x2 = __ldcs((const float2*)(pos + i));
    float2 y2 = __ldcs((const float2*)(pos + n + i));
    float2 w2 = __ldcs((const float2*)(nsx + i));
    float2 h2 = __ldcs((const float2*)(nsy + i));
    int2   p2 = __ldcs((const int2*)(pw + i));

    float2 r;
    r.x = node_area(x2.x, y2.x, w2.x, h2.x, (float)p2.x * INV_UPC);
    r.y = node_area(x2.y, y2.y, w2.y, h2.y, (float)p2.y * INV_UPC);
    __stcs((float2*)(out + i), r);
}

extern "C" void kernel_launch(void* const* d_in, const int* in_sizes, int n_in,
                              void* d_out, int out_size)
{
    const float* pos  = (const float*)d_in[0];
    const float* nsx  = (const float*)d_in[1];
    const float* nsy  = (const float*)d_in[2];
    const float* umap = (const float*)d_in[3];
    const int*   pw   = (const int*)d_in[4];
    float*       out  = (float*)d_out;

    int n = in_sizes[1];  // node_size_x has N elements

    // Pass 1: build the half-precision quad map (2 entries/thread)
    {
        int total = NBX * NBY / 2;
        int threads = 256;
        int blocks = (total + threads - 1) / threads;
        build_quad_kernel<<<blocks, threads>>>(umap);
    }

    // Pass 2: flat, 2 nodes/thread, 8B gather per node
    {
        int threads = 256;
        int elems_per_block = threads * 2;
        int blocks = (n + elems_per_block - 1) / elems_per_block;
        node_area_kernel_v13<<<blocks, threads>>>(pos, nsx, nsy, pw, out, n);
    }
}

// round 14
// speedup vs baseline: 1.1226x; 1.0214x over previous
#include <cuda_runtime.h>
#include <cuda_bf16.h>
#include <cuda_fp16.h>
#include <math.h>

// Problem constants (match reference)
#define NBX     512
#define NBY     512
#define BSX     1.953125f   // 1000/512, exact in fp32
#define BSY     1.953125f
#define INV_BS  0.512f      // rn(1/BSX); floor corrected exactly below
#define INV_UPC 10.0f       // 1 / UNIT_PIN_CAP

// Half-precision quad map: Q[bx][by] = {u00,u01,u10,u11} packed into a uint2
// (two half2 words, 8B). +1 clips baked in. 2 MB static device scratch.
__device__ uint2 g_quad_h[NBX * NBY];

__device__ __forceinline__ unsigned pack_half2(float a, float b) {
    __half2 h = __floats2half2_rn(a, b);
    return *reinterpret_cast<unsigned*>(&h);
}

__device__ __forceinline__ float2 unpack_half2(unsigned w) {
    __half2 h = *reinterpret_cast<__half2*>(&w);
    return __half22float2(h);
}

// Prep: 4 quad entries per thread, same bx row, vectorized loads/stores.
// Thread t handles entries [4t, 4t+4) = row bx, columns by0..by0+3.
__global__ __launch_bounds__(256) void build_quad_kernel_v2(
    const float* __restrict__ umap)
{
    int t = blockIdx.x * blockDim.x + threadIdx.x;
    int idx0 = t * 4;
    if (idx0 >= NBX * NBY) return;

    int bx  = idx0 >> 9;
    int by0 = idx0 & (NBY - 1);       // multiple of 4
    int bx1 = min(bx + 1, NBX - 1);

    const float* r0 = umap + bx  * NBY;
    const float* r1 = umap + bx1 * NBY;

    // Aligned float4 covering by0..by0+3, plus the +1 neighbor (by0+4, or
    // clipped to by0+3 == 511 at the row end).
    float4 a0 = __ldg((const float4*)(r0 + by0));
    float4 a1 = __ldg((const float4*)(r1 + by0));
    int bynext = min(by0 + 4, NBY - 1);
    float e0 = __ldg(r0 + bynext);
    float e1 = __ldg(r1 + bynext);

    float u0[5] = {a0.x, a0.y, a0.z, a0.w, e0};
    float u1[5] = {a1.x, a1.y, a1.z, a1.w, e1};

    uint4 q01, q23;
    q01.x = pack_half2(u0[0], u0[1]);
    q01.y = pack_half2(u1[0], u1[1]);
    q01.z = pack_half2(u0[1], u0[2]);
    q01.w = pack_half2(u1[1], u1[2]);
    q23.x = pack_half2(u0[2], u0[3]);
    q23.y = pack_half2(u1[2], u1[3]);
    q23.z = pack_half2(u0[3], u0[4]);
    q23.w = pack_half2(u1[3], u1[4]);

    uint4* dst = (uint4*)&g_quad_h[idx0];
    dst[0] = q01;
    dst[1] = q23;
}

// Branchless exact floor of x/BS: fast product then exact correction
// (b*BSX exactly representable for integer b in [0,512]). Provably equals
// floorf(div.rn(x, BSX)) for x in [0, 999).
__device__ __forceinline__ float exact_bin_floor(float x) {
    float fb = floorf(x * INV_BS);
    fb += ((fb + 1.0f) * BSX <= x) ? 1.0f : 0.0f;
    fb -= (fb * BSX > x)           ? 1.0f : 0.0f;
    return fb;
}

__device__ __forceinline__ float node_area(
    float x, float y, float w, float h, float ps)
{
    float fbx = exact_bin_floor(x);
    float fby = exact_bin_floor(y);

    float hix = x + w;
    float hiy = y + h;

    // Overlaps use UNCLIPPED bin positions (as in reference)
    float blx0 = fbx * BSX;
    float ox0 = fmaxf(fminf(hix, blx0 + BSX)        - fmaxf(x, blx0),       0.0f);
    float ox1 = fmaxf(fminf(hix, blx0 + 2.0f * BSX) - fmaxf(x, blx0 + BSX), 0.0f);

    float bly0 = fby * BSY;
    float oy0 = fmaxf(fminf(hiy, bly0 + BSY)        - fmaxf(y, bly0),       0.0f);
    float oy1 = fmaxf(fminf(hiy, bly0 + 2.0f * BSY) - fmaxf(y, bly0 + BSY), 0.0f);

    // x,y in [0,999) -> indices already in [0,511]; +1 clip baked into map.
    int qidx = ((int)fbx << 9) | (int)fby;

    // Single 8-byte gather (one LDG.64).
    uint2 q = __ldg(&g_quad_h[qidx]);

    float2 ulo = unpack_half2(q.x);  // u00,u01
    float2 uhi = unpack_half2(q.y);  // u10,u11

    float area = ox0 * (oy0 * ulo.x + oy1 * ulo.y)
               + ox1 * (oy0 * uhi.x + oy1 * uhi.y);

    return __fdividef(area * ps, w * h);
}

// Best measured main kernel (v12): grid-stride, register double-buffered
// streaming prefetch, 2 nodes per thread.
__global__ __launch_bounds__(256, 6) void node_area_kernel_v14(
    const float* __restrict__ pos,        // [2N]: x then y
    const float* __restrict__ nsx,        // [N]
    const float* __restrict__ nsy,        // [N]
    const int*   __restrict__ pw,         // [N]
    float*       __restrict__ out,        // [N]
    int n)
{
    int i = (blockIdx.x * blockDim.x + threadIdx.x) * 2;
    int stride = gridDim.x * blockDim.x * 2;

    if (i >= n) return;

    float2 x2 = *(const float2*)(pos + i);
    float2 y2 = *(const float2*)(pos + n + i);
    float2 w2 = *(const float2*)(nsx + i);
    float2 h2 = *(const float2*)(nsy + i);
    int2   p2 = *(const int2*)(pw + i);

    while (true) {
        int inext = i + stride;
        bool more = inext < n;

        float2 nx, ny, nw, nh; int2 np;
        if (more) {
            nx = *(const float2*)(pos + inext);
            ny = *(const float2*)(pos + n + inext);
            nw = *(const float2*)(nsx + inext);
            nh = *(const float2*)(nsy + inext);
            np = *(const int2*)(pw + inext);
        }

        float2 r;
        r.x = node_area(x2.x, y2.x, w2.x, h2.x, (float)p2.x * INV_UPC);
        r.y = node_area(x2.y, y2.y, w2.y, h2.y, (float)p2.y * INV_UPC);
        *(float2*)(out + i) = r;

        if (!more) break;
        x2 = nx; y2 = ny; w2 = nw; h2 = nh; p2 = np;
        i = inext;
    }
}

extern "C" void kernel_launch(void* const* d_in, const int* in_sizes, int n_in,
                              void* d_out, int out_size)
{
    const float* pos  = (const float*)d_in[0];
    const float* nsx  = (const float*)d_in[1];
    const float* nsy  = (const float*)d_in[2];
    const float* umap = (const float*)d_in[3];
    const int*   pw   = (const int*)d_in[4];
    float*       out  = (float*)d_out;

    int n = in_sizes[1];  // node_size_x has N elements

    // Pass 1: build the half-precision quad map (4 entries/thread, vectorized)
    {
        int total = NBX * NBY / 4;
        int threads = 256;
        int blocks = (total + threads - 1) / threads;
        build_quad_kernel_v2<<<blocks, threads>>>(umap);
    }

    // Pass 2: grid-stride, register double-buffered, 8B gather per node
    {
        int threads = 256;
        int blocks = 148 * 6;
        node_area_kernel_v14<<<blocks, threads>>>(pos, nsx, nsy, pw, out, n);
    }
}